// round 6
// baseline (speedup 1.0000x reference)
#include <cuda_runtime.h>
#include <cuda_bf16.h>
#include <math.h>

#define BB 8
#define PP 15360
#define QQ 9216
#define HH 96
#define WW 96
#define NMODS 8

#define BP_ROWS 240
#define BP_CHUNKS 64               // 64 * 240 = 15360

// ---- scratch (static device globals; no allocation anywhere) ----
__device__ __align__(16) __nv_bfloat16 g_Sbf[(size_t)PP * QQ];   // 283 MB bf16 copy of S
__device__ __align__(16) float g_sens_part[BP_CHUNKS * QQ];
__device__ __align__(16) float g_inv_sens[QQ];
__device__ __align__(16) float g_img[BB * QQ];
__device__ __align__(16) float g_fp_part[4 * PP * 8];
__device__ __align__(16) float g_bp_part[BP_CHUNKS * BB * QQ];
__device__ __align__(16) float g_em[BB * QQ];
__device__ __align__(16) float g_hidden[BB * 32 * QQ];

// ---- packed f32x2 helpers ----
__device__ __forceinline__ void fma2(unsigned long long& d,
                                     unsigned long long a,
                                     unsigned long long b) {
    asm("fma.rn.f32x2 %0, %1, %2, %0;" : "+l"(d) : "l"(a), "l"(b));
}
__device__ __forceinline__ float pk_lo(unsigned long long v) {
    return __uint_as_float((unsigned)(v & 0xffffffffu));
}
__device__ __forceinline__ float pk_hi(unsigned long long v) {
    return __uint_as_float((unsigned)(v >> 32));
}
__device__ __forceinline__ unsigned long long splat2(float f) {
    unsigned long long r;
    asm("mov.b64 %0, {%1, %1};" : "=l"(r) : "r"(__float_as_uint(f)));
    return r;
}
// bf16x2 word -> f32x2 pair (exact: bf16 is fp32 truncated to upper 16 bits)
__device__ __forceinline__ unsigned long long bf2pair(unsigned w) {
    unsigned lo = w << 16;
    unsigned hi = w & 0xffff0000u;
    unsigned long long r;
    asm("mov.b64 %0, {%1, %2};" : "=l"(r) : "r"(lo), "r"(hi));
    return r;
}

__global__ void k_init_img() {
    int n = blockIdx.x * 256 + threadIdx.x;
    g_img[n] = 1.f;
}

// ---- one-time: convert S fp32 -> bf16 AND accumulate fp32 column sums ----
__global__ __launch_bounds__(256) void k_conv_sens(const float* __restrict__ S) {
    const int col4 = blockIdx.x * 256 + threadIdx.x;   // float4 column, 0..2303
    const int chunk = blockIdx.y;                      // 0..63
    const int p0 = chunk * BP_ROWS;
    const float4* src = (const float4*)S + (size_t)p0 * 2304 + col4;
    uint2* dst = (uint2*)g_Sbf + (size_t)p0 * 2304 + col4;

    float4 sum = make_float4(0.f, 0.f, 0.f, 0.f);
    float4 c = src[0];
    float4 n1 = src[2304];
    #pragma unroll 4
    for (int r = 0; r < BP_ROWS; r++) {
        float4 n2;
        if (r < BP_ROWS - 2) n2 = src[(size_t)(r + 2) * 2304];
        sum.x += c.x; sum.y += c.y; sum.z += c.z; sum.w += c.w;
        __nv_bfloat162 h0 = __floats2bfloat162_rn(c.x, c.y);
        __nv_bfloat162 h1 = __floats2bfloat162_rn(c.z, c.w);
        uint2 o;
        o.x = *(unsigned*)&h0;
        o.y = *(unsigned*)&h1;
        dst[(size_t)r * 2304] = o;
        c = n1; n1 = n2;
    }
    ((float4*)g_sens_part)[(size_t)chunk * 2304 + col4] = sum;
}

// ---- forward projection (quarter-q split, bf16 S): fp_part[qt][p][b] ----
// 256 threads, 8 warps x 4 rows, img quarter staged in smem as f32 pairs (72 KB).
__global__ __launch_bounds__(256, 2) void k_fp() {
    extern __shared__ unsigned long long s_imgp[];   // [8 * 1152] f32 pairs
    const int qt = blockIdx.y;

    const float2* img2 = (const float2*)g_img;   // 4608 pairs per batch
    for (int j = threadIdx.x; j < 8 * 1152; j += 256) {
        int b = j / 1152;
        int i = j - b * 1152;
        ((float2*)s_imgp)[j] = img2[b * 4608 + qt * 1152 + i];
    }
    __syncthreads();

    const int warp = threadIdx.x >> 5, lane = threadIdx.x & 31;
    const int p0 = blockIdx.x * 32 + warp * 4;

    // bf16 row = 1152 x 16B units; quarter = 288 units; 9 k-steps of 32 lanes
    const ulonglong2* r0 = (const ulonglong2*)g_Sbf + (size_t)p0 * 1152 + qt * 288;
    const ulonglong2* r1 = r0 + 1152;
    const ulonglong2* r2 = r0 + 2304;
    const ulonglong2* r3 = r0 + 3456;

    unsigned long long acc[4][8];
    #pragma unroll
    for (int r = 0; r < 4; r++)
        #pragma unroll
        for (int b = 0; b < 8; b++) acc[r][b] = 0ull;

    ulonglong2 c0 = r0[lane], c1 = r1[lane], c2 = r2[lane], c3 = r3[lane];
    #pragma unroll
    for (int k = 0; k < 9; k++) {
        ulonglong2 n0, n1, n2, n3;
        if (k < 8) {
            n0 = r0[lane + (k + 1) * 32];
            n1 = r1[lane + (k + 1) * 32];
            n2 = r2[lane + (k + 1) * 32];
            n3 = r3[lane + (k + 1) * 32];
        }
        const int unit = lane + k * 32;
        #pragma unroll
        for (int w = 0; w < 4; w++) {
            unsigned w0 = (w < 2) ? ((w & 1) ? (unsigned)(c0.x >> 32) : (unsigned)c0.x)
                                  : ((w & 1) ? (unsigned)(c0.y >> 32) : (unsigned)c0.y);
            unsigned w1_ = (w < 2) ? ((w & 1) ? (unsigned)(c1.x >> 32) : (unsigned)c1.x)
                                   : ((w & 1) ? (unsigned)(c1.y >> 32) : (unsigned)c1.y);
            unsigned w2_ = (w < 2) ? ((w & 1) ? (unsigned)(c2.x >> 32) : (unsigned)c2.x)
                                   : ((w & 1) ? (unsigned)(c2.y >> 32) : (unsigned)c2.y);
            unsigned w3_ = (w < 2) ? ((w & 1) ? (unsigned)(c3.x >> 32) : (unsigned)c3.x)
                                   : ((w & 1) ? (unsigned)(c3.y >> 32) : (unsigned)c3.y);
            unsigned long long s0 = bf2pair(w0);
            unsigned long long s1 = bf2pair(w1_);
            unsigned long long s2 = bf2pair(w2_);
            unsigned long long s3 = bf2pair(w3_);
            const unsigned long long* ip = s_imgp + unit * 4 + w;
            #pragma unroll
            for (int b = 0; b < 8; b++) {
                unsigned long long iv = ip[b * 1152];
                fma2(acc[0][b], s0, iv);
                fma2(acc[1][b], s1, iv);
                fma2(acc[2][b], s2, iv);
                fma2(acc[3][b], s3, iv);
            }
        }
        c0 = n0; c1 = n1; c2 = n2; c3 = n3;
    }

    #pragma unroll
    for (int r = 0; r < 4; r++) {
        #pragma unroll
        for (int b = 0; b < 8; b++) {
            float v = pk_lo(acc[r][b]) + pk_hi(acc[r][b]);
            #pragma unroll
            for (int off = 16; off > 0; off >>= 1)
                v += __shfl_xor_sync(0xffffffffu, v, off);
            if (lane == 0)
                g_fp_part[qt * (PP * 8) + (p0 + r) * 8 + b] = v;
        }
    }
}

// ---- backprojection (ratio inline, bf16 S): partials per 240-row chunk ----
__global__ __launch_bounds__(256, 4) void k_bp(const float* __restrict__ sino) {
    __shared__ unsigned long long s_ratio[BP_ROWS * 8];   // splatted f32x2
    const int p0 = blockIdx.y * BP_ROWS;

    for (int j = threadIdx.x; j < BP_ROWS * 8; j += 256) {
        int p = p0 + (j >> 3), b = j & 7;
        float fp = g_fp_part[p * 8 + b]
                 + g_fp_part[1 * (PP * 8) + p * 8 + b]
                 + g_fp_part[2 * (PP * 8) + p * 8 + b]
                 + g_fp_part[3 * (PP * 8) + p * 8 + b];
        float rv = (fp > 0.f) ? sino[b * PP + p] / fp : 0.f;
        s_ratio[j] = splat2(rv);
    }
    __syncthreads();

    const int qi = blockIdx.x * 256 + threadIdx.x;   // uint2 column (8B = 4 bf16)
    const uint2* S2 = (const uint2*)g_Sbf;           // 2304 uint2 per row

    unsigned long long acc0[8], acc1[8];
    #pragma unroll
    for (int b = 0; b < 8; b++) { acc0[b] = 0ull; acc1[b] = 0ull; }

    uint2 cur = S2[(size_t)p0 * 2304 + qi];
    uint2 nx1 = S2[(size_t)(p0 + 1) * 2304 + qi];
    #pragma unroll 4
    for (int r = 0; r < BP_ROWS; r++) {
        uint2 nx2;
        if (r < BP_ROWS - 2) nx2 = S2[(size_t)(p0 + r + 2) * 2304 + qi];
        unsigned long long s0 = bf2pair(cur.x);   // q0,q1
        unsigned long long s1 = bf2pair(cur.y);   // q2,q3
        const unsigned long long* rp = s_ratio + r * 8;
        #pragma unroll
        for (int b = 0; b < 8; b++) {
            unsigned long long rv = rp[b];
            fma2(acc0[b], s0, rv);
            fma2(acc1[b], s1, rv);
        }
        cur = nx1; nx1 = nx2;
    }

    float4* bp4 = (float4*)g_bp_part;
    const int chunk = blockIdx.y;
    #pragma unroll
    for (int b = 0; b < 8; b++) {
        float4 o;
        o.x = pk_lo(acc0[b]); o.y = pk_hi(acc0[b]);
        o.z = pk_lo(acc1[b]); o.w = pk_hi(acc1[b]);
        bp4[(size_t)(chunk * 8 + b) * 2304 + qi] = o;
    }
}

// ---- fused: reduce bp partials -> em image, then conv1 (1->32 3x3+relu) ----
__global__ __launch_bounds__(256) void k_emc1(const float* __restrict__ w1,
                                              const float* __restrict__ b1,
                                              int first) {
    __shared__ float s_w[288];
    __shared__ float s_b[32];
    for (int j = threadIdx.x; j < 288; j += 256) s_w[j] = w1[j];
    if (threadIdx.x < 32) s_b[threadIdx.x] = b1[threadIdx.x];
    __syncthreads();

    const int n = blockIdx.x * 256 + threadIdx.x;
    const int q = n % QQ;
    const int b = n / QQ;

    float inv;
    if (first) {
        float sv = 0.f;
        #pragma unroll 16
        for (int c = 0; c < BP_CHUNKS; c++) sv += g_sens_part[c * QQ + q];
        inv = (sv != 0.f) ? 1.f / sv : 0.f;
        g_inv_sens[q] = inv;
    } else {
        inv = g_inv_sens[q];
    }
    float s = 0.f;
    #pragma unroll 16
    for (int c = 0; c < BP_CHUNKS; c++)
        s += g_bp_part[(size_t)c * (BB * QQ) + n];
    g_em[n] = g_img[n] * inv * s;

    const int y = q / WW, x = q % WW;
    float v[9];
    #pragma unroll
    for (int dy = 0; dy < 3; dy++)
        #pragma unroll
        for (int dx = 0; dx < 3; dx++) {
            int yy = y + dy - 1, xx = x + dx - 1;
            v[dy * 3 + dx] = (yy >= 0 && yy < HH && xx >= 0 && xx < WW)
                                 ? g_img[b * QQ + yy * WW + xx] : 0.f;
        }
    #pragma unroll 4
    for (int c = 0; c < 32; c++) {
        float a = s_b[c];
        #pragma unroll
        for (int k = 0; k < 9; k++) a += v[k] * s_w[c * 9 + k];
        g_hidden[(b * 32 + c) * QQ + q] = fmaxf(a, 0.f);
    }
}

// ---- conv2 (32->1 3x3 SAME) fused with FBSEM fusion ----
__global__ __launch_bounds__(384) void k_conv2f(const float* __restrict__ w2,
                                                const float* __restrict__ b2,
                                                const float* __restrict__ beta,
                                                float* __restrict__ out,
                                                int write_out) {
    __shared__ float s_w[288];
    __shared__ float s_h[6 * 100];
    const int b = blockIdx.x / 24, strip = blockIdx.x % 24;
    const int y0 = strip * 4;

    if (threadIdx.x < 288) s_w[threadIdx.x] = w2[threadIdx.x];
    const float bias = b2[0];
    const float bt = beta[0];

    const int py = threadIdx.x / 96;
    const int px = threadIdx.x % 96;
    float acc = bias;

    for (int c = 0; c < 32; c++) {
        __syncthreads();
        const float* hsrc = g_hidden + (size_t)(b * 32 + c) * QQ;
        for (int j = threadIdx.x; j < 588; j += 384) {
            int ty = j / 98, tx = j % 98;
            int yy = y0 - 1 + ty, xx = tx - 1;
            s_h[ty * 100 + tx] = (yy >= 0 && yy < HH && xx >= 0 && xx < WW)
                                     ? hsrc[yy * WW + xx] : 0.f;
        }
        __syncthreads();
        const float* wc = s_w + c * 9;
        float a = 0.f;
        #pragma unroll
        for (int dy = 0; dy < 3; dy++)
            #pragma unroll
            for (int dx = 0; dx < 3; dx++)
                a += s_h[(py + dy) * 100 + px + dx] * wc[dy * 3 + dx];
        acc += a;
    }

    const int q = (y0 + py) * WW + px;
    const int n = b * QQ + q;
    const float inv = g_inv_sens[q];
    const float b2i = bt * bt * inv;
    const float em = g_em[n];
    const float t = 1.f - b2i * acc;
    const float val = 2.f * em / (t + sqrtf(t * t + 4.f * b2i * em));
    g_img[n] = val;
    if (write_out) out[n] = val;
}

extern "C" void kernel_launch(void* const* d_in, const int* in_sizes, int n_in,
                              void* d_out, int out_size) {
    const float* sino = (const float*)d_in[0];
    const float* S    = (const float*)d_in[1];
    const float* w1   = (const float*)d_in[2];
    const float* b1   = (const float*)d_in[3];
    const float* w2   = (const float*)d_in[4];
    const float* b2   = (const float*)d_in[5];
    const float* beta = (const float*)d_in[6];
    float* out = (float*)d_out;

    const int fp_smem = 8 * 1152 * 8;   // 73728 B
    cudaFuncSetAttribute(k_fp, cudaFuncAttributeMaxDynamicSharedMemorySize,
                         fp_smem);

    k_conv_sens<<<dim3(9, 64), 256>>>(S);
    k_init_img<<<288, 256>>>();

    for (int it = 0; it < NMODS; it++) {
        k_fp<<<dim3(PP / 32, 4), 256, fp_smem>>>();
        k_bp<<<dim3(9, BP_CHUNKS), 256>>>(sino);
        k_emc1<<<288, 256>>>(w1, b1, it == 0 ? 1 : 0);
        k_conv2f<<<192, 384>>>(w2, b2, beta, out, (it == NMODS - 1) ? 1 : 0);
    }
}

// round 8
// speedup vs baseline: 1.4091x; 1.4091x over previous
#include <cuda_runtime.h>
#include <cuda_bf16.h>
#include <math.h>
#include <cstdint>

#define BB 8
#define PP 15360
#define QQ 9216
#define HH 96
#define WW 96
#define NMODS 8

// ---- scratch (static device globals; no allocation anywhere) ----
__device__ __align__(16) __nv_bfloat16 g_Sbf[(size_t)PP * QQ];   // S bf16 [p][q]
__device__ __align__(16) __nv_bfloat16 g_St [(size_t)QQ * PP];   // S^T bf16 [q][p]
__device__ __align__(16) __nv_bfloat16 g_imgbf[BB * QQ];         // img bf16 [b][q]
__device__ __align__(16) __nv_bfloat16 g_ratbf[BB * PP];         // ratio bf16 [b][p]
__device__ __align__(16) float g_sens_part[240 * QQ];
__device__ __align__(16) float g_inv_sens[QQ];
__device__ __align__(16) float g_img[BB * QQ];
__device__ __align__(16) float g_fp_part[4 * PP * 8];            // [kslice][p*8+b]
__device__ __align__(16) float g_bp_part[4 * QQ * 8];            // [kslice][q*8+b]
__device__ __align__(16) float g_em[BB * QQ];
__device__ __align__(16) float g_hidden[BB * 32 * QQ];

// ---- warp-level bf16 MMA (baseline PTX, compiles to HMMA on sm_103) ----
__device__ __forceinline__ void mma16816(float* d,
                                         uint32_t a0, uint32_t a1,
                                         uint32_t a2, uint32_t a3,
                                         uint32_t b0, uint32_t b1) {
    asm volatile(
        "mma.sync.aligned.m16n8k16.row.col.f32.bf16.bf16.f32 "
        "{%0,%1,%2,%3}, {%4,%5,%6,%7}, {%8,%9}, {%0,%1,%2,%3};"
        : "+f"(d[0]), "+f"(d[1]), "+f"(d[2]), "+f"(d[3])
        : "r"(a0), "r"(a1), "r"(a2), "r"(a3), "r"(b0), "r"(b1));
}

// ================= one-time prep: S -> bf16 (row + transposed) + col sums ====
__global__ __launch_bounds__(256) void k_prep(const float* __restrict__ S) {
    __shared__ float tile[64][65];
    __shared__ float red[256];
    const int qx0 = blockIdx.x * 64;   // 144 tiles
    const int px0 = blockIdx.y * 64;   // 240 tiles
    const int t = threadIdx.x;
    const int jr0 = t >> 6, jcol = t & 63;

    float part = 0.f;
    #pragma unroll 4
    for (int k = 0; k < 16; k++) {
        int i = k * 4 + jr0;
        float v = S[(size_t)(px0 + i) * QQ + qx0 + jcol];
        tile[i][jcol] = v;
        part += v;
        g_Sbf[(size_t)(px0 + i) * QQ + qx0 + jcol] = __float2bfloat16(v);
    }
    red[t] = part;
    __syncthreads();
    if (t < 64) {
        float s = red[t] + red[t + 64] + red[t + 128] + red[t + 192];
        g_sens_part[(size_t)blockIdx.y * QQ + qx0 + t] = s;
    }
    #pragma unroll 4
    for (int k = 0; k < 16; k++) {
        int jr = k * 4 + jr0;
        g_St[(size_t)(qx0 + jr) * PP + px0 + jcol] =
            __float2bfloat16(tile[jcol][jr]);
    }
}

__global__ void k_sens_fin() {
    int q = blockIdx.x * 256 + threadIdx.x;
    float s = 0.f;
    #pragma unroll 16
    for (int c = 0; c < 240; c++) s += g_sens_part[(size_t)c * QQ + q];
    g_inv_sens[q] = (s != 0.f) ? 1.f / s : 0.f;
}

__global__ void k_init() {
    int n = blockIdx.x * 256 + threadIdx.x;   // 73728 = BB*QQ
    g_img[n] = 1.f;
    g_imgbf[n] = __float2bfloat16(1.f);
}

// ================= HMMA GEMM: out[m*8+b] = sum_k A[m,k]*B[b,k] ================
// MODE 0: fp (A=g_Sbf [P,Q], B=img), MODE 1: bp (A=g_St [Q,P], B=ratio).
// grid (M/128, 4): 4 k-slices; 256 thr = 8 warps x 16 rows.
// Per 32-k block, lane(t=lane&3, g=lane>>2) loads 16B A rows g,g+8 at col t*8
// and 16B of B row g; the column permutation is identical on A and B, so the
// dot product is unchanged.
template <int MODE>
__global__ __launch_bounds__(256) void k_gemm() {
    const int lane = threadIdx.x & 31, warp = threadIdx.x >> 5;
    const int g = lane >> 2, t = lane & 3;
    constexpr int LDA = MODE ? PP : QQ;         // elements per A row
    constexpr int KC  = MODE ? 3840 : 2304;     // k per CTA (LDA/4)
    constexpr int NIT = KC / 32;
    constexpr int S4  = LDA / 8;                // uint4 per A row
    const __nv_bfloat16* A = MODE ? g_St : g_Sbf;
    const __nv_bfloat16* B = MODE ? g_ratbf : g_imgbf;
    float* out = (MODE ? g_bp_part : g_fp_part) + blockIdx.y * (LDA == PP ? QQ * 8 : PP * 8);
    // note: out rows = M = (MODE ? QQ : PP)
    const int m0 = blockIdx.x * 128 + warp * 16;
    const int k0 = blockIdx.y * KC;

    const uint4* pa = (const uint4*)(A + (size_t)(m0 + g) * LDA + k0) + t;
    const uint4* pa8 = (const uint4*)(A + (size_t)(m0 + g + 8) * LDA + k0) + t;
    const uint4* pb = (const uint4*)(B + (size_t)g * LDA + k0) + t;

    float d[4] = {0.f, 0.f, 0.f, 0.f};

    #pragma unroll 4
    for (int i = 0; i < NIT; i++) {
        uint4 a = pa[i * 4];
        uint4 a8 = pa8[i * 4];
        uint4 b = pb[i * 4];
        mma16816(d, a.x, a8.x, a.y, a8.y, b.x, b.y);
        mma16816(d, a.z, a8.z, a.w, a8.w, b.z, b.w);
    }

    float2 lo = make_float2(d[0], d[1]);
    float2 hi = make_float2(d[2], d[3]);
    *(float2*)(out + (size_t)(m0 + g) * 8 + t * 2) = lo;
    *(float2*)(out + (size_t)(m0 + g + 8) * 8 + t * 2) = hi;
}

// ================= ratio: bf16(sino/fp) =================
__global__ void k_ratio(const float* __restrict__ sino) {
    int n = blockIdx.x * 256 + threadIdx.x;   // 0 .. PP*8-1, layout [p*8+b]
    int p = n >> 3, b = n & 7;
    float fpv = g_fp_part[n] + g_fp_part[PP * 8 + n]
              + g_fp_part[2 * PP * 8 + n] + g_fp_part[3 * PP * 8 + n];
    float rv = (fpv > 0.f) ? sino[b * PP + p] / fpv : 0.f;
    g_ratbf[b * PP + p] = __float2bfloat16(rv);
}

// ================= em + conv1 fused =================
__global__ __launch_bounds__(256) void k_emc1(const float* __restrict__ w1,
                                              const float* __restrict__ b1) {
    __shared__ float s_w[288];
    __shared__ float s_b[32];
    for (int j = threadIdx.x; j < 288; j += 256) s_w[j] = w1[j];
    if (threadIdx.x < 32) s_b[threadIdx.x] = b1[threadIdx.x];
    __syncthreads();

    const int n = blockIdx.x * 256 + threadIdx.x;
    const int q = n % QQ;
    const int b = n / QQ;

    const float inv = g_inv_sens[q];
    const int m = q * 8 + b;
    const float s = g_bp_part[m] + g_bp_part[QQ * 8 + m]
                  + g_bp_part[2 * QQ * 8 + m] + g_bp_part[3 * QQ * 8 + m];
    g_em[n] = g_img[n] * inv * s;

    const int y = q / WW, x = q % WW;
    float v[9];
    #pragma unroll
    for (int dy = 0; dy < 3; dy++)
        #pragma unroll
        for (int dx = 0; dx < 3; dx++) {
            int yy = y + dy - 1, xx = x + dx - 1;
            v[dy * 3 + dx] = (yy >= 0 && yy < HH && xx >= 0 && xx < WW)
                                 ? g_img[b * QQ + yy * WW + xx] : 0.f;
        }
    #pragma unroll 4
    for (int c = 0; c < 32; c++) {
        float a = s_b[c];
        #pragma unroll
        for (int k = 0; k < 9; k++) a += v[k] * s_w[c * 9 + k];
        g_hidden[(b * 32 + c) * QQ + q] = fmaxf(a, 0.f);
    }
}

// ================= conv2 + FBSEM fusion =================
__global__ __launch_bounds__(384) void k_conv2f(const float* __restrict__ w2,
                                                const float* __restrict__ b2,
                                                const float* __restrict__ beta,
                                                float* __restrict__ out,
                                                int write_out) {
    __shared__ float s_w[288];
    __shared__ float s_h[6 * 100];
    const int b = blockIdx.x / 24, strip = blockIdx.x % 24;
    const int y0 = strip * 4;

    if (threadIdx.x < 288) s_w[threadIdx.x] = w2[threadIdx.x];
    const float bias = b2[0];
    const float bt = beta[0];

    const int py = threadIdx.x / 96;
    const int px = threadIdx.x % 96;
    float acc = bias;

    for (int c = 0; c < 32; c++) {
        __syncthreads();
        const float* hsrc = g_hidden + (size_t)(b * 32 + c) * QQ;
        for (int j = threadIdx.x; j < 588; j += 384) {
            int ty = j / 98, tx = j % 98;
            int yy = y0 - 1 + ty, xx = tx - 1;
            s_h[ty * 100 + tx] = (yy >= 0 && yy < HH && xx >= 0 && xx < WW)
                                     ? hsrc[yy * WW + xx] : 0.f;
        }
        __syncthreads();
        const float* wc = s_w + c * 9;
        float a = 0.f;
        #pragma unroll
        for (int dy = 0; dy < 3; dy++)
            #pragma unroll
            for (int dx = 0; dx < 3; dx++)
                a += s_h[(py + dy) * 100 + px + dx] * wc[dy * 3 + dx];
        acc += a;
    }

    const int q = (y0 + py) * WW + px;
    const int n = b * QQ + q;
    const float inv = g_inv_sens[q];
    const float b2i = bt * bt * inv;
    const float em = g_em[n];
    const float t = 1.f - b2i * acc;
    const float val = 2.f * em / (t + sqrtf(t * t + 4.f * b2i * em));
    g_img[n] = val;
    g_imgbf[n] = __float2bfloat16(val);
    if (write_out) out[n] = val;
}

extern "C" void kernel_launch(void* const* d_in, const int* in_sizes, int n_in,
                              void* d_out, int out_size) {
    const float* sino = (const float*)d_in[0];
    const float* S    = (const float*)d_in[1];
    const float* w1   = (const float*)d_in[2];
    const float* b1   = (const float*)d_in[3];
    const float* w2   = (const float*)d_in[4];
    const float* b2   = (const float*)d_in[5];
    const float* beta = (const float*)d_in[6];
    float* out = (float*)d_out;

    k_prep<<<dim3(144, 240), 256>>>(S);
    k_sens_fin<<<36, 256>>>();
    k_init<<<288, 256>>>();

    for (int it = 0; it < NMODS; it++) {
        k_gemm<0><<<dim3(120, 4), 256>>>();   // fp: [P,8] partials over 4 k-slices
        k_ratio<<<480, 256>>>(sino);
        k_gemm<1><<<dim3(72, 4), 256>>>();    // bp: [Q,8] partials over 4 k-slices
        k_emc1<<<288, 256>>>(w1, b1);
        k_conv2f<<<192, 384>>>(w2, b2, beta, out, (it == NMODS - 1) ? 1 : 0);
    }
}